// round 16
// baseline (speedup 1.0000x reference)
#include <cuda_runtime.h>
#include <cuda_fp16.h>
#include <math.h>

#define N_NODES 50000
#define N_EDGES 600000
#define IN_DIM 256
#define HID 128
#define OUT_DIM 10
#define BN_EPS 1e-5f

#define SCAN_TILE 1024
#define N_TILES ((N_NODES + SCAN_TILE - 1) / SCAN_TILE)  // 49

// ---------------- scratch (static __device__ — no allocations) ----------------
__device__ __half g_h[N_NODES * HID];       // residual activations (fp16)
__device__ __half g_hwh[N_NODES * HID];     // h @ Wc (fp16, gather source)
__device__ float  g_t[N_NODES * HID];       // conv output pre-BN (fp32)
__device__ int    g_deg[N_NODES];
__device__ int    g_rowptr[N_NODES + 1];
__device__ int    g_cursor[N_NODES];
__device__ float  g_dinv[N_NODES];
__device__ unsigned long long g_csr[N_EDGES];   // packed (w<<32 | s*HID)
__device__ float  g_sum[3 * HID];
__device__ float  g_sumsq[3 * HID];
__device__ int    g_tilesum[N_TILES];
__device__ int    g_tileoff[N_TILES + 1];
__device__ int    g_ticket;
__device__ int    g_scan_flag;
__device__ int    g_is64;

// -------- detect edge dtype + reset scan sync ---------------------------------
__global__ void detect_kernel(const void* ei) {
    __shared__ int bad;
    if (threadIdx.x == 0) bad = 0;
    __syncthreads();
    const long long* p = (const long long*)ei;
    for (int i = threadIdx.x; i < 4096; i += blockDim.x) {
        long long v = p[i];
        if (v < 0 || v >= N_NODES) atomicExch(&bad, 1);
    }
    __syncthreads();
    if (threadIdx.x == 0) {
        g_is64 = bad ? 0 : 1;
        g_ticket = 0;
        g_scan_flag = 0;
    }
}

__device__ __forceinline__ void load_edge(const void* ei, int e, int& s, int& d) {
    if (g_is64) {
        const long long* p = (const long long*)ei;
        s = (int)p[e];
        d = (int)p[N_EDGES + e];
    } else {
        const int* p = (const int*)ei;
        s = p[e];
        d = p[N_EDGES + e];
    }
}

__global__ void count_deg_kernel(const void* ei) {
    for (int e = blockIdx.x * blockDim.x + threadIdx.x; e < N_EDGES;
         e += gridDim.x * blockDim.x) {
        int d;
        if (g_is64) d = (int)((const long long*)ei)[N_EDGES + e];
        else        d = ((const int*)ei)[N_EDGES + e];
        atomicAdd(&g_deg[d], 1);
    }
}

// ---- merged scan: tile sums -> (last block) scan -> spin -> write rowptr ----
__global__ __launch_bounds__(SCAN_TILE)
void scan_write_kernel() {
    __shared__ int wsum[32];
    __shared__ int is_last;
    int tid = threadIdx.x, lane = tid & 31, wid = tid >> 5;
    int i = blockIdx.x * SCAN_TILE + tid;
    int d = (i < N_NODES) ? g_deg[i] : 0;

    int incl = d;
    #pragma unroll
    for (int off = 1; off < 32; off <<= 1) {
        int v = __shfl_up_sync(0xffffffffu, incl, off);
        if (lane >= off) incl += v;
    }
    if (lane == 31) wsum[wid] = incl;
    __syncthreads();
    if (wid == 0) {
        int v = wsum[lane];
        int wi = v;
        #pragma unroll
        for (int off = 1; off < 32; off <<= 1) {
            int t2 = __shfl_up_sync(0xffffffffu, wi, off);
            if (lane >= off) wi += t2;
        }
        wsum[lane] = wi - v;
        if (lane == 31) {
            g_tilesum[blockIdx.x] = wi;
            __threadfence();
            int t = atomicAdd(&g_ticket, 1);
            is_last = (t == N_TILES - 1);
        }
    }
    __syncthreads();

    if (is_last && wid == 0) {
        int run = 0;
        for (int base = 0; base < N_TILES; base += 32) {
            int idx = base + lane;
            int val = (idx < N_TILES) ? g_tilesum[idx] : 0;
            int inc2 = val;
            #pragma unroll
            for (int off = 1; off < 32; off <<= 1) {
                int t2 = __shfl_up_sync(0xffffffffu, inc2, off);
                if (lane >= off) inc2 += t2;
            }
            if (idx < N_TILES) g_tileoff[idx] = run + inc2 - val;
            int tot = __shfl_sync(0xffffffffu, inc2, 31);
            run += tot;
        }
        if (lane == 0) {
            g_tileoff[N_TILES] = run;
            __threadfence();
            atomicExch(&g_scan_flag, 1);
        }
    }

    if (tid == 0) {
        while (atomicAdd(&g_scan_flag, 0) == 0) { }
    }
    __syncthreads();

    int excl = g_tileoff[blockIdx.x] + wsum[wid] + incl - d;
    if (i < N_NODES) {
        g_rowptr[i] = excl;
        g_cursor[i] = excl;
        g_dinv[i]   = rsqrtf((float)d + 1.0f);
    }
    if (i == N_NODES - 1) g_rowptr[N_NODES] = g_tileoff[N_TILES];
}

__global__ void build_csr_kernel(const void* ei) {
    for (int e = blockIdx.x * blockDim.x + threadIdx.x; e < N_EDGES;
         e += gridDim.x * blockDim.x) {
        int s, d;
        load_edge(ei, e, s, d);
        int pos = atomicAdd(&g_cursor[d], 1);
        float w = g_dinv[s];
        unsigned long long rec =
            ((unsigned long long)__float_as_uint(w) << 32) | (unsigned)(s * HID);
        g_csr[pos] = rec;
    }
}

// ---------------- fp16 tensor-core GEMM pieces --------------------------------
#define SA 20
#define SB 136
#define SAH 68

#define MMA_FP16(acc, a, b) \
    asm volatile( \
        "mma.sync.aligned.m16n8k16.row.col.f32.f16.f16.f32 " \
        "{%0,%1,%2,%3}, {%4,%5,%6,%7}, {%8,%9}, {%0,%1,%2,%3};" \
        : "+f"((acc)[0]), "+f"((acc)[1]), "+f"((acc)[2]), "+f"((acc)[3]) \
        : "r"((a)[0]), "r"((a)[1]), "r"((a)[2]), "r"((a)[3]), \
          "r"((b)[0]), "r"((b)[1]))

// ---- fused input GEMM + conv0 GEMM: hw = (relu(x@W_in + b_in)) @ Wc0 --------
__global__ __launch_bounds__(256)
void gemm_in0_kernel(const float* __restrict__ x, const float* __restrict__ W_in,
                     const float* __restrict__ b_in, const float* __restrict__ Wc0,
                     __half* __restrict__ hw_out) {
    __shared__ unsigned pool[128 * SAH + 16 * SB];  // 43.5 KB
    unsigned* Ah = pool;
    unsigned* As = pool;
    unsigned* Bs = pool + 128 * SAH;

    int tid = threadIdx.x;
    int w = tid >> 5, lane = tid & 31;
    int wm = (w & 1) * 64;
    int wn = (w >> 1) * 32;
    int gid = lane >> 2, tig = lane & 3;
    int row0 = blockIdx.x * 128;

    int a_r  = tid >> 3;
    int a_kk = (tid & 7) * 4;
    int b_k2 = tid >> 5;
    int b_c  = (tid & 31) * 4;

    float acc[4][4][4];
    #pragma unroll
    for (int i = 0; i < 4; i++)
        #pragma unroll
        for (int j = 0; j < 4; j++)
            #pragma unroll
            for (int c = 0; c < 4; c++) acc[i][j][c] = 0.f;

    float4 a_reg[4];
    float4 blo_reg[2], bhi_reg[2];

    auto load_g = [&](int k0) {
        #pragma unroll
        for (int p = 0; p < 4; p++) {
            int grow = row0 + p * 32 + a_r;
            float4 v = make_float4(0.f, 0.f, 0.f, 0.f);
            if (grow < N_NODES)
                v = *(const float4*)&x[(size_t)grow * IN_DIM + k0 + a_kk];
            a_reg[p] = v;
        }
        #pragma unroll
        for (int p = 0; p < 2; p++) {
            int k2 = p * 8 + b_k2;
            blo_reg[p] = *(const float4*)&W_in[(size_t)(k0 + 2 * k2)     * HID + b_c];
            bhi_reg[p] = *(const float4*)&W_in[(size_t)(k0 + 2 * k2 + 1) * HID + b_c];
        }
    };

    auto store_s = [&]() {
        #pragma unroll
        for (int p = 0; p < 4; p++) {
            int r = p * 32 + a_r;
            float4 v = a_reg[p];
            __half2 h0 = __floats2half2_rn(v.x, v.y);
            __half2 h1 = __floats2half2_rn(v.z, v.w);
            uint2 u = make_uint2(*(unsigned*)&h0, *(unsigned*)&h1);
            *(uint2*)&As[r * SA + (a_kk >> 1)] = u;
        }
        #pragma unroll
        for (int p = 0; p < 2; p++) {
            int k2 = p * 8 + b_k2;
            float4 lo = blo_reg[p], hi = bhi_reg[p];
            __half2 q0 = __floats2half2_rn(lo.x, hi.x);
            __half2 q1 = __floats2half2_rn(lo.y, hi.y);
            __half2 q2 = __floats2half2_rn(lo.z, hi.z);
            __half2 q3 = __floats2half2_rn(lo.w, hi.w);
            uint4 u = make_uint4(*(unsigned*)&q0, *(unsigned*)&q1,
                                 *(unsigned*)&q2, *(unsigned*)&q3);
            *(uint4*)&Bs[k2 * SB + b_c] = u;
        }
    };

    // ---- stage 1: h = relu(x @ W_in + b_in), K = 256 ----
    load_g(0);
    for (int k0 = 0; k0 < IN_DIM; k0 += 32) {
        store_s();
        __syncthreads();
        if (k0 + 32 < IN_DIM) load_g(k0 + 32);
        #pragma unroll
        for (int s = 0; s < 2; s++) {
            int base = s * 8;
            unsigned afr[4][4], bfr[4][2];
            #pragma unroll
            for (int i = 0; i < 4; i++) {
                int m = wm + i * 16;
                afr[i][0] = As[(m + gid)     * SA + base + tig];
                afr[i][1] = As[(m + gid + 8) * SA + base + tig];
                afr[i][2] = As[(m + gid)     * SA + base + tig + 4];
                afr[i][3] = As[(m + gid + 8) * SA + base + tig + 4];
            }
            #pragma unroll
            for (int j = 0; j < 4; j++) {
                int n = wn + j * 8 + gid;
                bfr[j][0] = Bs[(base + tig)     * SB + n];
                bfr[j][1] = Bs[(base + tig + 4) * SB + n];
            }
            #pragma unroll
            for (int i = 0; i < 4; i++)
                #pragma unroll
                for (int j = 0; j < 4; j++)
                    MMA_FP16(acc[i][j], afr[i], bfr[j]);
        }
        __syncthreads();
    }

    // ---- h tile -> Ah (fp16, bias+relu); reset acc ----
    #pragma unroll
    for (int i = 0; i < 4; i++) {
        int r_up = wm + i * 16 + gid;
        int r_dn = r_up + 8;
        #pragma unroll
        for (int j = 0; j < 4; j++) {
            int col = wn + j * 8 + 2 * tig;
            float b0 = b_in[col], b1 = b_in[col + 1];
            float u0 = fmaxf(acc[i][j][0] + b0, 0.f);
            float u1 = fmaxf(acc[i][j][1] + b1, 0.f);
            float d0 = fmaxf(acc[i][j][2] + b0, 0.f);
            float d1 = fmaxf(acc[i][j][3] + b1, 0.f);
            __half2 hu = __floats2half2_rn(u0, u1);
            __half2 hd = __floats2half2_rn(d0, d1);
            Ah[r_up * SAH + (col >> 1)] = *(unsigned*)&hu;
            Ah[r_dn * SAH + (col >> 1)] = *(unsigned*)&hd;
            acc[i][j][0] = 0.f; acc[i][j][1] = 0.f;
            acc[i][j][2] = 0.f; acc[i][j][3] = 0.f;
        }
    }
    __syncthreads();

    // ---- stage 2: hw = h @ Wc0, K = 128, A from Ah ----
    for (int kc = 0; kc < 4; kc++) {
        int k0 = kc * 32;
        #pragma unroll
        for (int p = 0; p < 2; p++) {
            int k2 = p * 8 + b_k2;
            float4 lo = *(const float4*)&Wc0[(size_t)(k0 + 2 * k2)     * HID + b_c];
            float4 hi = *(const float4*)&Wc0[(size_t)(k0 + 2 * k2 + 1) * HID + b_c];
            __half2 q0 = __floats2half2_rn(lo.x, hi.x);
            __half2 q1 = __floats2half2_rn(lo.y, hi.y);
            __half2 q2 = __floats2half2_rn(lo.z, hi.z);
            __half2 q3 = __floats2half2_rn(lo.w, hi.w);
            uint4 u = make_uint4(*(unsigned*)&q0, *(unsigned*)&q1,
                                 *(unsigned*)&q2, *(unsigned*)&q3);
            *(uint4*)&Bs[k2 * SB + b_c] = u;
        }
        __syncthreads();
        #pragma unroll
        for (int s = 0; s < 2; s++) {
            int kbase = (k0 >> 1) + s * 8;
            unsigned afr[4][4], bfr[4][2];
            #pragma unroll
            for (int i = 0; i < 4; i++) {
                int m = wm + i * 16;
                afr[i][0] = Ah[(m + gid)     * SAH + kbase + tig];
                afr[i][1] = Ah[(m + gid + 8) * SAH + kbase + tig];
                afr[i][2] = Ah[(m + gid)     * SAH + kbase + tig + 4];
                afr[i][3] = Ah[(m + gid + 8) * SAH + kbase + tig + 4];
            }
            #pragma unroll
            for (int j = 0; j < 4; j++) {
                int n = wn + j * 8 + gid;
                bfr[j][0] = Bs[(s * 8 + tig)     * SB + n];
                bfr[j][1] = Bs[(s * 8 + tig + 4) * SB + n];
            }
            #pragma unroll
            for (int i = 0; i < 4; i++)
                #pragma unroll
                for (int j = 0; j < 4; j++)
                    MMA_FP16(acc[i][j], afr[i], bfr[j]);
        }
        __syncthreads();
    }

    // ---- epilogue: hw fp16 ----
    #pragma unroll
    for (int i = 0; i < 4; i++) {
        int r_up = row0 + wm + i * 16 + gid;
        int r_dn = r_up + 8;
        #pragma unroll
        for (int j = 0; j < 4; j++) {
            int col = wn + j * 8 + 2 * tig;
            if (r_up < N_NODES)
                *(__half2*)&hw_out[(size_t)r_up * HID + col] =
                    __floats2half2_rn(acc[i][j][0], acc[i][j][1]);
            if (r_dn < N_NODES)
                *(__half2*)&hw_out[(size_t)r_dn * HID + col] =
                    __floats2half2_rn(acc[i][j][2], acc[i][j][3]);
        }
    }
}

// ---- general GEMM with fused BN+relu(+res) A-build (layers 1,2) -------------
// t_in fp32; hres/h_out fp16 (residual buffer)
__global__ __launch_bounds__(256)
void gemm_fp16_kernel(const float* __restrict__ W, __half* __restrict__ C_half,
                      const float* __restrict__ t_in,
                      const float* __restrict__ st_sum, const float* __restrict__ st_sq,
                      const float* __restrict__ gma, const float* __restrict__ bta,
                      const __half* __restrict__ hres, __half* __restrict__ h_out,
                      int add_res) {
    __shared__ unsigned As[128 * SA];
    __shared__ unsigned Bs[16 * SB];
    __shared__ float s_sc[HID], s_sh[HID];
    const int K = HID;

    int tid = threadIdx.x;
    int w = tid >> 5, lane = tid & 31;
    int wm = (w & 1) * 64;
    int wn = (w >> 1) * 32;
    int gid = lane >> 2, tig = lane & 3;
    int row0 = blockIdx.x * 128;

    int a_r  = tid >> 3;
    int a_kk = (tid & 7) * 4;
    int b_k2 = tid >> 5;
    int b_c  = (tid & 31) * 4;

    float4 a_reg[4];
    float4 blo_reg[2], bhi_reg[2];

    auto load_W = [&](int k0) {
        #pragma unroll
        for (int p = 0; p < 2; p++) {
            int k2 = p * 8 + b_k2;
            blo_reg[p] = *(const float4*)&W[(size_t)(k0 + 2 * k2)     * HID + b_c];
            bhi_reg[p] = *(const float4*)&W[(size_t)(k0 + 2 * k2 + 1) * HID + b_c];
        }
    };

    auto load_A = [&](int k0) {
        #pragma unroll
        for (int p = 0; p < 4; p++) {
            int grow = row0 + p * 32 + a_r;
            float4 v = make_float4(0.f, 0.f, 0.f, 0.f);
            if (grow < N_NODES) {
                size_t off = (size_t)grow * K + k0 + a_kk;
                int c = k0 + a_kk;
                float4 tv = *(const float4*)&t_in[off];
                v.x = fmaxf(tv.x * s_sc[c + 0] + s_sh[c + 0], 0.f);
                v.y = fmaxf(tv.y * s_sc[c + 1] + s_sh[c + 1], 0.f);
                v.z = fmaxf(tv.z * s_sc[c + 2] + s_sh[c + 2], 0.f);
                v.w = fmaxf(tv.w * s_sc[c + 3] + s_sh[c + 3], 0.f);
                if (add_res) {
                    uint2 ru = *(const uint2*)&hres[off];
                    float2 r01 = __half22float2(*(const __half2*)&ru.x);
                    float2 r23 = __half22float2(*(const __half2*)&ru.y);
                    v.x += r01.x; v.y += r01.y; v.z += r23.x; v.w += r23.y;
                }
                __half2 o0 = __floats2half2_rn(v.x, v.y);
                __half2 o1 = __floats2half2_rn(v.z, v.w);
                *(uint2*)&h_out[off] =
                    make_uint2(*(unsigned*)&o0, *(unsigned*)&o1);
            }
            a_reg[p] = v;
        }
    };

    auto store_smem = [&]() {
        #pragma unroll
        for (int p = 0; p < 4; p++) {
            int r = p * 32 + a_r;
            float4 v = a_reg[p];
            __half2 h0 = __floats2half2_rn(v.x, v.y);
            __half2 h1 = __floats2half2_rn(v.z, v.w);
            uint2 u = make_uint2(*(unsigned*)&h0, *(unsigned*)&h1);
            *(uint2*)&As[r * SA + (a_kk >> 1)] = u;
        }
        #pragma unroll
        for (int p = 0; p < 2; p++) {
            int k2 = p * 8 + b_k2;
            float4 lo = blo_reg[p], hi = bhi_reg[p];
            __half2 q0 = __floats2half2_rn(lo.x, hi.x);
            __half2 q1 = __floats2half2_rn(lo.y, hi.y);
            __half2 q2 = __floats2half2_rn(lo.z, hi.z);
            __half2 q3 = __floats2half2_rn(lo.w, hi.w);
            uint4 u = make_uint4(*(unsigned*)&q0, *(unsigned*)&q1,
                                 *(unsigned*)&q2, *(unsigned*)&q3);
            *(uint4*)&Bs[k2 * SB + b_c] = u;
        }
    };

    float acc[4][4][4];
    #pragma unroll
    for (int i = 0; i < 4; i++)
        #pragma unroll
        for (int j = 0; j < 4; j++)
            #pragma unroll
            for (int c = 0; c < 4; c++) acc[i][j][c] = 0.f;

    load_W(0);

    if (tid < HID) {
        float mu  = st_sum[tid] * (1.0f / N_NODES);
        float var = st_sq[tid] * (1.0f / N_NODES) - mu * mu;
        float sc  = gma[tid] * rsqrtf(var + BN_EPS);
        s_sc[tid] = sc;
        s_sh[tid] = bta[tid] - mu * sc;
    }
    __syncthreads();

    load_A(0);
    for (int k0 = 0; k0 < K; k0 += 32) {
        store_smem();
        __syncthreads();
        if (k0 + 32 < K) { load_W(k0 + 32); load_A(k0 + 32); }
        #pragma unroll
        for (int s = 0; s < 2; s++) {
            int base = s * 8;
            unsigned afr[4][4], bfr[4][2];
            #pragma unroll
            for (int i = 0; i < 4; i++) {
                int m = wm + i * 16;
                afr[i][0] = As[(m + gid)     * SA + base + tig];
                afr[i][1] = As[(m + gid + 8) * SA + base + tig];
                afr[i][2] = As[(m + gid)     * SA + base + tig + 4];
                afr[i][3] = As[(m + gid + 8) * SA + base + tig + 4];
            }
            #pragma unroll
            for (int j = 0; j < 4; j++) {
                int n = wn + j * 8 + gid;
                bfr[j][0] = Bs[(base + tig)     * SB + n];
                bfr[j][1] = Bs[(base + tig + 4) * SB + n];
            }
            #pragma unroll
            for (int i = 0; i < 4; i++)
                #pragma unroll
                for (int j = 0; j < 4; j++)
                    MMA_FP16(acc[i][j], afr[i], bfr[j]);
        }
        __syncthreads();
    }

    #pragma unroll
    for (int i = 0; i < 4; i++) {
        int r_up = row0 + wm + i * 16 + gid;
        int r_dn = r_up + 8;
        #pragma unroll
        for (int j = 0; j < 4; j++) {
            int col = wn + j * 8 + 2 * tig;
            if (r_up < N_NODES)
                *(__half2*)&C_half[(size_t)r_up * HID + col] =
                    __floats2half2_rn(acc[i][j][0], acc[i][j][1]);
            if (r_dn < N_NODES)
                *(__half2*)&C_half[(size_t)r_dn * HID + col] =
                    __floats2half2_rn(acc[i][j][2], acc[i][j][3]);
        }
    }
}

// ---- aggregation: warp/node, explicit gather double-buffer --------------------
__global__ __launch_bounds__(256)
void agg_kernel(const __half* __restrict__ hw, const float* __restrict__ bc,
                float* __restrict__ t, float* __restrict__ st_sum,
                float* __restrict__ st_sq) {
    __shared__ float s_sum[HID], s_sq[HID];
    int tid = threadIdx.x;
    if (tid < HID) { s_sum[tid] = 0.f; s_sq[tid] = 0.f; }

    int lane = tid & 31;
    int n = blockIdx.x * 8 + (tid >> 5);

    int e0 = 0, e1 = 0;
    float di = 0.f;
    unsigned long long r0 = 0, r1 = 0, r2 = 0, r3 = 0;
    uint2 u_buf = make_uint2(0u, 0u);
    float w_buf = 0.f;
    if (n < N_NODES) {
        e0 = g_rowptr[n];
        e1 = g_rowptr[n + 1];
        di = g_dinv[n];
        if (e0 < e1)     r0 = __ldg(&g_csr[e0]);
        if (e0 + 1 < e1) r1 = __ldg(&g_csr[e0 + 1]);
        if (e0 + 2 < e1) r2 = __ldg(&g_csr[e0 + 2]);
        if (e0 + 3 < e1) r3 = __ldg(&g_csr[e0 + 3]);
        // issue first gather
        if (e0 < e1) {
            w_buf = __uint_as_float((unsigned)(r0 >> 32));
            u_buf = __ldg((const uint2*)(hw + (unsigned)r0) + lane);
        }
    }
    __syncthreads();   // s_sum/s_sq init visible

    if (n < N_NODES) {
        float a0 = 0.f, a1 = 0.f, a2 = 0.f, a3 = 0.f;
        for (int e = e0; e < e1; e++) {
            // advance record queue
            unsigned long long rec_next = r1;
            r0 = r1; r1 = r2; r2 = r3;
            if (e + 4 < e1) r3 = __ldg(&g_csr[e + 4]);
            // consume current gather, issue next BEFORE accumulating
            uint2 u_cur = u_buf;
            float wgt   = w_buf;
            if (e + 1 < e1) {
                w_buf = __uint_as_float((unsigned)(rec_next >> 32));
                u_buf = __ldg((const uint2*)(hw + (unsigned)rec_next) + lane);
            }
            float2 f0 = __half22float2(*(const __half2*)&u_cur.x);
            float2 f1 = __half22float2(*(const __half2*)&u_cur.y);
            a0 += f0.x * wgt; a1 += f0.y * wgt; a2 += f1.x * wgt; a3 += f1.y * wgt;
        }
        float dii = di * di;
        int c = lane * 4;
        uint2 su = __ldg((const uint2*)(hw + (size_t)n * HID) + lane);
        float2 sf0 = __half22float2(*(const __half2*)&su.x);
        float2 sf1 = __half22float2(*(const __half2*)&su.y);
        float t0 = a0 * di + sf0.x * dii + bc[c + 0];
        float t1 = a1 * di + sf0.y * dii + bc[c + 1];
        float t2 = a2 * di + sf1.x * dii + bc[c + 2];
        float t3 = a3 * di + sf1.y * dii + bc[c + 3];
        *(float4*)(t + (size_t)n * HID + c) = make_float4(t0, t1, t2, t3);
        atomicAdd(&s_sum[c + 0], t0); atomicAdd(&s_sq[c + 0], t0 * t0);
        atomicAdd(&s_sum[c + 1], t1); atomicAdd(&s_sq[c + 1], t1 * t1);
        atomicAdd(&s_sum[c + 2], t2); atomicAdd(&s_sq[c + 2], t2 * t2);
        atomicAdd(&s_sum[c + 3], t3); atomicAdd(&s_sq[c + 3], t3 * t3);
    }
    __syncthreads();
    if (tid < HID) {
        atomicAdd(&st_sum[tid], s_sum[tid]);
        atomicAdd(&st_sq[tid],  s_sq[tid]);
    }
}

// ------- output projection fused with final BN+relu+residual (hres fp16) ------
__global__ __launch_bounds__(256)
void out_kernel(const float* __restrict__ t, const __half* __restrict__ hres,
                const float* __restrict__ st_sum, const float* __restrict__ st_sq,
                const float* __restrict__ gma, const float* __restrict__ bta,
                const float* __restrict__ Wo, const float* __restrict__ bo,
                float* __restrict__ out) {
    __shared__ float ws[HID * OUT_DIM];
    __shared__ float bs[OUT_DIM];
    __shared__ float s_sc[HID], s_sh[HID];
    int tid = threadIdx.x;
    for (int i = tid; i < HID * OUT_DIM; i += blockDim.x) ws[i] = Wo[i];
    if (tid < OUT_DIM) bs[tid] = bo[tid];
    if (tid < HID) {
        float mu  = st_sum[tid] * (1.0f / N_NODES);
        float var = st_sq[tid] * (1.0f / N_NODES) - mu * mu;
        float sc  = gma[tid] * rsqrtf(var + BN_EPS);
        s_sc[tid] = sc;
        s_sh[tid] = bta[tid] - mu * sc;
    }
    __syncthreads();
    int n = blockIdx.x * blockDim.x + tid;
    if (n >= N_NODES) return;
    float acc[OUT_DIM];
    #pragma unroll
    for (int o = 0; o < OUT_DIM; o++) acc[o] = bs[o];
    const float4* tp = (const float4*)(t + (size_t)n * HID);
    const uint2* rp = (const uint2*)(hres + (size_t)n * HID);
    #pragma unroll 4
    for (int k4 = 0; k4 < HID / 4; k4++) {
        float4 tv = tp[k4];
        uint2 ru = rp[k4];
        float2 r01 = __half22float2(*(const __half2*)&ru.x);
        float2 r23 = __half22float2(*(const __half2*)&ru.y);
        int kb = k4 * 4;
        float a0 = fmaxf(tv.x * s_sc[kb + 0] + s_sh[kb + 0], 0.f) + r01.x;
        float a1 = fmaxf(tv.y * s_sc[kb + 1] + s_sh[kb + 1], 0.f) + r01.y;
        float a2 = fmaxf(tv.z * s_sc[kb + 2] + s_sh[kb + 2], 0.f) + r23.x;
        float a3 = fmaxf(tv.w * s_sc[kb + 3] + s_sh[kb + 3], 0.f) + r23.y;
        #pragma unroll
        for (int o = 0; o < OUT_DIM; o++) {
            acc[o] += a0 * ws[(kb + 0) * OUT_DIM + o]
                    + a1 * ws[(kb + 1) * OUT_DIM + o]
                    + a2 * ws[(kb + 2) * OUT_DIM + o]
                    + a3 * ws[(kb + 3) * OUT_DIM + o];
        }
    }
    #pragma unroll
    for (int o = 0; o < OUT_DIM; o++) out[n * OUT_DIM + o] = acc[o];
}

// ---------------- launch ----------------
extern "C" void kernel_launch(void* const* d_in, const int* in_sizes, int n_in,
                              void* d_out, int out_size) {
    const float* x     = (const float*)d_in[0];
    const void*  ei    = d_in[1];
    const float* W_in  = (const float*)d_in[2];
    const float* b_in  = (const float*)d_in[3];
    const float* Wc    = (const float*)d_in[4];
    const float* bc    = (const float*)d_in[5];
    const float* gamma = (const float*)d_in[6];
    const float* beta  = (const float*)d_in[7];
    const float* W_out = (const float*)d_in[8];
    const float* b_out = (const float*)d_in[9];
    float* out = (float*)d_out;

    float *p_t, *p_sum, *p_sq;
    __half *p_hwh, *p_h;
    int* p_deg;
    cudaGetSymbolAddress((void**)&p_h,   g_h);
    cudaGetSymbolAddress((void**)&p_hwh, g_hwh);
    cudaGetSymbolAddress((void**)&p_t,   g_t);
    cudaGetSymbolAddress((void**)&p_sum, g_sum);
    cudaGetSymbolAddress((void**)&p_sq,  g_sumsq);
    cudaGetSymbolAddress((void**)&p_deg, g_deg);

    static cudaStream_t s_side = nullptr;
    static cudaEvent_t ev_fork = nullptr, ev_join = nullptr;
    if (!s_side) {
        cudaStreamCreateWithFlags(&s_side, cudaStreamNonBlocking);
        cudaEventCreateWithFlags(&ev_fork, cudaEventDisableTiming);
        cudaEventCreateWithFlags(&ev_join, cudaEventDisableTiming);
    }

    // BN stats zero: main stream (completes long before agg0)
    cudaMemsetAsync(p_sum, 0, 3 * HID * sizeof(float), 0);
    cudaMemsetAsync(p_sq,  0, 3 * HID * sizeof(float), 0);

    // fork: CSR build on side stream, overlapped with fused input+conv0 GEMM
    cudaEventRecord(ev_fork, 0);
    cudaStreamWaitEvent(s_side, ev_fork, 0);
    cudaMemsetAsync(p_deg, 0, N_NODES * sizeof(int), s_side);
    detect_kernel<<<1, 256, 0, s_side>>>(ei);
    count_deg_kernel<<<586, 1024, 0, s_side>>>(ei);
    scan_write_kernel<<<N_TILES, SCAN_TILE, 0, s_side>>>();
    build_csr_kernel<<<586, 1024, 0, s_side>>>(ei);
    cudaEventRecord(ev_join, s_side);

    int grid = (N_NODES + 127) / 128;
    int agrid = (N_NODES + 7) / 8;

    // fused: hw (fp16) = relu(x @ W_in + b_in) @ Wc0
    gemm_in0_kernel<<<grid, 256>>>(x, W_in, b_in, Wc, p_hwh);

    // join: agg needs CSR
    cudaStreamWaitEvent(0, ev_join, 0);
    agg_kernel<<<agrid, 256>>>(p_hwh, bc, p_t, p_sum, p_sq);

    // layer 1: BN(stats0)+relu fused A-build, writes h1 (fp16) + hw fp16
    gemm_fp16_kernel<<<grid, 256>>>(Wc + 1 * HID * HID, p_hwh,
                                    p_t, p_sum, p_sq, gamma, beta,
                                    nullptr, p_h, 0);
    agg_kernel<<<agrid, 256>>>(p_hwh, bc + HID, p_t, p_sum + HID, p_sq + HID);

    // layer 2: BN(stats1)+relu+res(h1) fused A-build, writes h2 (fp16) + hw fp16
    gemm_fp16_kernel<<<grid, 256>>>(Wc + 2 * HID * HID, p_hwh,
                                    p_t, p_sum + HID, p_sq + HID,
                                    gamma + HID, beta + HID,
                                    p_h, p_h, 1);
    agg_kernel<<<agrid, 256>>>(p_hwh, bc + 2 * HID, p_t,
                               p_sum + 2 * HID, p_sq + 2 * HID);

    // output: fused BN(stats2)+relu+res(h2) then @ W_out + b_out
    out_kernel<<<(N_NODES + 255) / 256, 256>>>(p_t, p_h,
                                               p_sum + 2 * HID, p_sq + 2 * HID,
                                               gamma + 2 * HID, beta + 2 * HID,
                                               W_out, b_out, out);
}

// round 17
// speedup vs baseline: 1.1149x; 1.1149x over previous
#include <cuda_runtime.h>
#include <cuda_fp16.h>
#include <math.h>

#define N_NODES 50000
#define N_EDGES 600000
#define IN_DIM 256
#define HID 128
#define OUT_DIM 10
#define BN_EPS 1e-5f

#define SCAN_TILE 1024
#define N_TILES ((N_NODES + SCAN_TILE - 1) / SCAN_TILE)  // 49

// ---------------- scratch (static __device__ — no allocations) ----------------
__device__ __half g_h[N_NODES * HID];       // residual activations (fp16)
__device__ __half g_hwh[N_NODES * HID];     // h @ Wc (fp16, gather source)
__device__ float  g_t[N_NODES * HID];       // conv output pre-BN (fp32)
__device__ int    g_deg[N_NODES];
__device__ int    g_rowptr[N_NODES + 1];
__device__ int    g_cursor[N_NODES];
__device__ float  g_dinv[N_NODES];
__device__ unsigned long long g_csr[N_EDGES];   // packed (w<<32 | s*HID)
__device__ float  g_sum[3 * HID];
__device__ float  g_sumsq[3 * HID];
__device__ int    g_tilesum[N_TILES];
__device__ int    g_tileoff[N_TILES + 1];
__device__ int    g_ticket;
__device__ int    g_scan_flag;
__device__ int    g_is64;

// -------- detect edge dtype + reset scan sync ---------------------------------
__global__ void detect_kernel(const void* ei) {
    __shared__ int bad;
    if (threadIdx.x == 0) bad = 0;
    __syncthreads();
    const long long* p = (const long long*)ei;
    for (int i = threadIdx.x; i < 4096; i += blockDim.x) {
        long long v = p[i];
        if (v < 0 || v >= N_NODES) atomicExch(&bad, 1);
    }
    __syncthreads();
    if (threadIdx.x == 0) {
        g_is64 = bad ? 0 : 1;
        g_ticket = 0;
        g_scan_flag = 0;
    }
}

__device__ __forceinline__ void load_edge(const void* ei, int e, int& s, int& d) {
    if (g_is64) {
        const long long* p = (const long long*)ei;
        s = (int)p[e];
        d = (int)p[N_EDGES + e];
    } else {
        const int* p = (const int*)ei;
        s = p[e];
        d = p[N_EDGES + e];
    }
}

__global__ void count_deg_kernel(const void* ei) {
    for (int e = blockIdx.x * blockDim.x + threadIdx.x; e < N_EDGES;
         e += gridDim.x * blockDim.x) {
        int d;
        if (g_is64) d = (int)((const long long*)ei)[N_EDGES + e];
        else        d = ((const int*)ei)[N_EDGES + e];
        atomicAdd(&g_deg[d], 1);
    }
}

// ---- merged scan: tile sums -> (last block) scan -> spin -> write rowptr ----
__global__ __launch_bounds__(SCAN_TILE)
void scan_write_kernel() {
    __shared__ int wsum[32];
    __shared__ int is_last;
    int tid = threadIdx.x, lane = tid & 31, wid = tid >> 5;
    int i = blockIdx.x * SCAN_TILE + tid;
    int d = (i < N_NODES) ? g_deg[i] : 0;

    int incl = d;
    #pragma unroll
    for (int off = 1; off < 32; off <<= 1) {
        int v = __shfl_up_sync(0xffffffffu, incl, off);
        if (lane >= off) incl += v;
    }
    if (lane == 31) wsum[wid] = incl;
    __syncthreads();
    if (wid == 0) {
        int v = wsum[lane];
        int wi = v;
        #pragma unroll
        for (int off = 1; off < 32; off <<= 1) {
            int t2 = __shfl_up_sync(0xffffffffu, wi, off);
            if (lane >= off) wi += t2;
        }
        wsum[lane] = wi - v;
        if (lane == 31) {
            g_tilesum[blockIdx.x] = wi;
            __threadfence();
            int t = atomicAdd(&g_ticket, 1);
            is_last = (t == N_TILES - 1);
        }
    }
    __syncthreads();

    if (is_last && wid == 0) {
        int run = 0;
        for (int base = 0; base < N_TILES; base += 32) {
            int idx = base + lane;
            int val = (idx < N_TILES) ? g_tilesum[idx] : 0;
            int inc2 = val;
            #pragma unroll
            for (int off = 1; off < 32; off <<= 1) {
                int t2 = __shfl_up_sync(0xffffffffu, inc2, off);
                if (lane >= off) inc2 += t2;
            }
            if (idx < N_TILES) g_tileoff[idx] = run + inc2 - val;
            int tot = __shfl_sync(0xffffffffu, inc2, 31);
            run += tot;
        }
        if (lane == 0) {
            g_tileoff[N_TILES] = run;
            __threadfence();
            atomicExch(&g_scan_flag, 1);
        }
    }

    if (tid == 0) {
        while (atomicAdd(&g_scan_flag, 0) == 0) { }
    }
    __syncthreads();

    int excl = g_tileoff[blockIdx.x] + wsum[wid] + incl - d;
    if (i < N_NODES) {
        g_rowptr[i] = excl;
        g_cursor[i] = excl;
        g_dinv[i]   = rsqrtf((float)d + 1.0f);
    }
    if (i == N_NODES - 1) g_rowptr[N_NODES] = g_tileoff[N_TILES];
}

__global__ void build_csr_kernel(const void* ei) {
    for (int e = blockIdx.x * blockDim.x + threadIdx.x; e < N_EDGES;
         e += gridDim.x * blockDim.x) {
        int s, d;
        load_edge(ei, e, s, d);
        int pos = atomicAdd(&g_cursor[d], 1);
        float w = g_dinv[s];
        unsigned long long rec =
            ((unsigned long long)__float_as_uint(w) << 32) | (unsigned)(s * HID);
        g_csr[pos] = rec;
    }
}

// ---------------- fp16 tensor-core GEMM pieces --------------------------------
#define SA 20
#define SB 136
#define SAH 68

#define MMA_FP16(acc, a, b) \
    asm volatile( \
        "mma.sync.aligned.m16n8k16.row.col.f32.f16.f16.f32 " \
        "{%0,%1,%2,%3}, {%4,%5,%6,%7}, {%8,%9}, {%0,%1,%2,%3};" \
        : "+f"((acc)[0]), "+f"((acc)[1]), "+f"((acc)[2]), "+f"((acc)[3]) \
        : "r"((a)[0]), "r"((a)[1]), "r"((a)[2]), "r"((a)[3]), \
          "r"((b)[0]), "r"((b)[1]))

// ---- fused input GEMM + conv0 GEMM: hw = (relu(x@W_in + b_in)) @ Wc0 --------
__global__ __launch_bounds__(256)
void gemm_in0_kernel(const float* __restrict__ x, const float* __restrict__ W_in,
                     const float* __restrict__ b_in, const float* __restrict__ Wc0,
                     __half* __restrict__ hw_out) {
    __shared__ unsigned pool[128 * SAH + 16 * SB];  // 43.5 KB
    unsigned* Ah = pool;
    unsigned* As = pool;
    unsigned* Bs = pool + 128 * SAH;

    int tid = threadIdx.x;
    int w = tid >> 5, lane = tid & 31;
    int wm = (w & 1) * 64;
    int wn = (w >> 1) * 32;
    int gid = lane >> 2, tig = lane & 3;
    int row0 = blockIdx.x * 128;

    int a_r  = tid >> 3;
    int a_kk = (tid & 7) * 4;
    int b_k2 = tid >> 5;
    int b_c  = (tid & 31) * 4;

    float acc[4][4][4];
    #pragma unroll
    for (int i = 0; i < 4; i++)
        #pragma unroll
        for (int j = 0; j < 4; j++)
            #pragma unroll
            for (int c = 0; c < 4; c++) acc[i][j][c] = 0.f;

    float4 a_reg[4];
    float4 blo_reg[2], bhi_reg[2];

    auto load_g = [&](int k0) {
        #pragma unroll
        for (int p = 0; p < 4; p++) {
            int grow = row0 + p * 32 + a_r;
            float4 v = make_float4(0.f, 0.f, 0.f, 0.f);
            if (grow < N_NODES)
                v = *(const float4*)&x[(size_t)grow * IN_DIM + k0 + a_kk];
            a_reg[p] = v;
        }
        #pragma unroll
        for (int p = 0; p < 2; p++) {
            int k2 = p * 8 + b_k2;
            blo_reg[p] = *(const float4*)&W_in[(size_t)(k0 + 2 * k2)     * HID + b_c];
            bhi_reg[p] = *(const float4*)&W_in[(size_t)(k0 + 2 * k2 + 1) * HID + b_c];
        }
    };

    auto store_s = [&]() {
        #pragma unroll
        for (int p = 0; p < 4; p++) {
            int r = p * 32 + a_r;
            float4 v = a_reg[p];
            __half2 h0 = __floats2half2_rn(v.x, v.y);
            __half2 h1 = __floats2half2_rn(v.z, v.w);
            uint2 u = make_uint2(*(unsigned*)&h0, *(unsigned*)&h1);
            *(uint2*)&As[r * SA + (a_kk >> 1)] = u;
        }
        #pragma unroll
        for (int p = 0; p < 2; p++) {
            int k2 = p * 8 + b_k2;
            float4 lo = blo_reg[p], hi = bhi_reg[p];
            __half2 q0 = __floats2half2_rn(lo.x, hi.x);
            __half2 q1 = __floats2half2_rn(lo.y, hi.y);
            __half2 q2 = __floats2half2_rn(lo.z, hi.z);
            __half2 q3 = __floats2half2_rn(lo.w, hi.w);
            uint4 u = make_uint4(*(unsigned*)&q0, *(unsigned*)&q1,
                                 *(unsigned*)&q2, *(unsigned*)&q3);
            *(uint4*)&Bs[k2 * SB + b_c] = u;
        }
    };

    // ---- stage 1: h = relu(x @ W_in + b_in), K = 256 ----
    load_g(0);
    for (int k0 = 0; k0 < IN_DIM; k0 += 32) {
        store_s();
        __syncthreads();
        if (k0 + 32 < IN_DIM) load_g(k0 + 32);
        #pragma unroll
        for (int s = 0; s < 2; s++) {
            int base = s * 8;
            unsigned afr[4][4], bfr[4][2];
            #pragma unroll
            for (int i = 0; i < 4; i++) {
                int m = wm + i * 16;
                afr[i][0] = As[(m + gid)     * SA + base + tig];
                afr[i][1] = As[(m + gid + 8) * SA + base + tig];
                afr[i][2] = As[(m + gid)     * SA + base + tig + 4];
                afr[i][3] = As[(m + gid + 8) * SA + base + tig + 4];
            }
            #pragma unroll
            for (int j = 0; j < 4; j++) {
                int n = wn + j * 8 + gid;
                bfr[j][0] = Bs[(base + tig)     * SB + n];
                bfr[j][1] = Bs[(base + tig + 4) * SB + n];
            }
            #pragma unroll
            for (int i = 0; i < 4; i++)
                #pragma unroll
                for (int j = 0; j < 4; j++)
                    MMA_FP16(acc[i][j], afr[i], bfr[j]);
        }
        __syncthreads();
    }

    // ---- h tile -> Ah (fp16, bias+relu); reset acc ----
    #pragma unroll
    for (int i = 0; i < 4; i++) {
        int r_up = wm + i * 16 + gid;
        int r_dn = r_up + 8;
        #pragma unroll
        for (int j = 0; j < 4; j++) {
            int col = wn + j * 8 + 2 * tig;
            float b0 = b_in[col], b1 = b_in[col + 1];
            float u0 = fmaxf(acc[i][j][0] + b0, 0.f);
            float u1 = fmaxf(acc[i][j][1] + b1, 0.f);
            float d0 = fmaxf(acc[i][j][2] + b0, 0.f);
            float d1 = fmaxf(acc[i][j][3] + b1, 0.f);
            __half2 hu = __floats2half2_rn(u0, u1);
            __half2 hd = __floats2half2_rn(d0, d1);
            Ah[r_up * SAH + (col >> 1)] = *(unsigned*)&hu;
            Ah[r_dn * SAH + (col >> 1)] = *(unsigned*)&hd;
            acc[i][j][0] = 0.f; acc[i][j][1] = 0.f;
            acc[i][j][2] = 0.f; acc[i][j][3] = 0.f;
        }
    }
    __syncthreads();

    // ---- stage 2: hw = h @ Wc0, K = 128, A from Ah ----
    for (int kc = 0; kc < 4; kc++) {
        int k0 = kc * 32;
        #pragma unroll
        for (int p = 0; p < 2; p++) {
            int k2 = p * 8 + b_k2;
            float4 lo = *(const float4*)&Wc0[(size_t)(k0 + 2 * k2)     * HID + b_c];
            float4 hi = *(const float4*)&Wc0[(size_t)(k0 + 2 * k2 + 1) * HID + b_c];
            __half2 q0 = __floats2half2_rn(lo.x, hi.x);
            __half2 q1 = __floats2half2_rn(lo.y, hi.y);
            __half2 q2 = __floats2half2_rn(lo.z, hi.z);
            __half2 q3 = __floats2half2_rn(lo.w, hi.w);
            uint4 u = make_uint4(*(unsigned*)&q0, *(unsigned*)&q1,
                                 *(unsigned*)&q2, *(unsigned*)&q3);
            *(uint4*)&Bs[k2 * SB + b_c] = u;
        }
        __syncthreads();
        #pragma unroll
        for (int s = 0; s < 2; s++) {
            int kbase = (k0 >> 1) + s * 8;
            unsigned afr[4][4], bfr[4][2];
            #pragma unroll
            for (int i = 0; i < 4; i++) {
                int m = wm + i * 16;
                afr[i][0] = Ah[(m + gid)     * SAH + kbase + tig];
                afr[i][1] = Ah[(m + gid + 8) * SAH + kbase + tig];
                afr[i][2] = Ah[(m + gid)     * SAH + kbase + tig + 4];
                afr[i][3] = Ah[(m + gid + 8) * SAH + kbase + tig + 4];
            }
            #pragma unroll
            for (int j = 0; j < 4; j++) {
                int n = wn + j * 8 + gid;
                bfr[j][0] = Bs[(s * 8 + tig)     * SB + n];
                bfr[j][1] = Bs[(s * 8 + tig + 4) * SB + n];
            }
            #pragma unroll
            for (int i = 0; i < 4; i++)
                #pragma unroll
                for (int j = 0; j < 4; j++)
                    MMA_FP16(acc[i][j], afr[i], bfr[j]);
        }
        __syncthreads();
    }

    // ---- epilogue: hw fp16 ----
    #pragma unroll
    for (int i = 0; i < 4; i++) {
        int r_up = row0 + wm + i * 16 + gid;
        int r_dn = r_up + 8;
        #pragma unroll
        for (int j = 0; j < 4; j++) {
            int col = wn + j * 8 + 2 * tig;
            if (r_up < N_NODES)
                *(__half2*)&hw_out[(size_t)r_up * HID + col] =
                    __floats2half2_rn(acc[i][j][0], acc[i][j][1]);
            if (r_dn < N_NODES)
                *(__half2*)&hw_out[(size_t)r_dn * HID + col] =
                    __floats2half2_rn(acc[i][j][2], acc[i][j][3]);
        }
    }
}

// ---- general GEMM with fused BN+relu(+res) A-build (layers 1,2) -------------
__global__ __launch_bounds__(256)
void gemm_fp16_kernel(const float* __restrict__ W, __half* __restrict__ C_half,
                      const float* __restrict__ t_in,
                      const float* __restrict__ st_sum, const float* __restrict__ st_sq,
                      const float* __restrict__ gma, const float* __restrict__ bta,
                      const __half* __restrict__ hres, __half* __restrict__ h_out,
                      int add_res) {
    __shared__ unsigned As[128 * SA];
    __shared__ unsigned Bs[16 * SB];
    __shared__ float s_sc[HID], s_sh[HID];
    const int K = HID;

    int tid = threadIdx.x;
    int w = tid >> 5, lane = tid & 31;
    int wm = (w & 1) * 64;
    int wn = (w >> 1) * 32;
    int gid = lane >> 2, tig = lane & 3;
    int row0 = blockIdx.x * 128;

    int a_r  = tid >> 3;
    int a_kk = (tid & 7) * 4;
    int b_k2 = tid >> 5;
    int b_c  = (tid & 31) * 4;

    float4 a_reg[4];
    float4 blo_reg[2], bhi_reg[2];

    auto load_W = [&](int k0) {
        #pragma unroll
        for (int p = 0; p < 2; p++) {
            int k2 = p * 8 + b_k2;
            blo_reg[p] = *(const float4*)&W[(size_t)(k0 + 2 * k2)     * HID + b_c];
            bhi_reg[p] = *(const float4*)&W[(size_t)(k0 + 2 * k2 + 1) * HID + b_c];
        }
    };

    auto load_A = [&](int k0) {
        #pragma unroll
        for (int p = 0; p < 4; p++) {
            int grow = row0 + p * 32 + a_r;
            float4 v = make_float4(0.f, 0.f, 0.f, 0.f);
            if (grow < N_NODES) {
                size_t off = (size_t)grow * K + k0 + a_kk;
                int c = k0 + a_kk;
                float4 tv = *(const float4*)&t_in[off];
                v.x = fmaxf(tv.x * s_sc[c + 0] + s_sh[c + 0], 0.f);
                v.y = fmaxf(tv.y * s_sc[c + 1] + s_sh[c + 1], 0.f);
                v.z = fmaxf(tv.z * s_sc[c + 2] + s_sh[c + 2], 0.f);
                v.w = fmaxf(tv.w * s_sc[c + 3] + s_sh[c + 3], 0.f);
                if (add_res) {
                    uint2 ru = *(const uint2*)&hres[off];
                    float2 r01 = __half22float2(*(const __half2*)&ru.x);
                    float2 r23 = __half22float2(*(const __half2*)&ru.y);
                    v.x += r01.x; v.y += r01.y; v.z += r23.x; v.w += r23.y;
                }
                __half2 o0 = __floats2half2_rn(v.x, v.y);
                __half2 o1 = __floats2half2_rn(v.z, v.w);
                *(uint2*)&h_out[off] =
                    make_uint2(*(unsigned*)&o0, *(unsigned*)&o1);
            }
            a_reg[p] = v;
        }
    };

    auto store_smem = [&]() {
        #pragma unroll
        for (int p = 0; p < 4; p++) {
            int r = p * 32 + a_r;
            float4 v = a_reg[p];
            __half2 h0 = __floats2half2_rn(v.x, v.y);
            __half2 h1 = __floats2half2_rn(v.z, v.w);
            uint2 u = make_uint2(*(unsigned*)&h0, *(unsigned*)&h1);
            *(uint2*)&As[r * SA + (a_kk >> 1)] = u;
        }
        #pragma unroll
        for (int p = 0; p < 2; p++) {
            int k2 = p * 8 + b_k2;
            float4 lo = blo_reg[p], hi = bhi_reg[p];
            __half2 q0 = __floats2half2_rn(lo.x, hi.x);
            __half2 q1 = __floats2half2_rn(lo.y, hi.y);
            __half2 q2 = __floats2half2_rn(lo.z, hi.z);
            __half2 q3 = __floats2half2_rn(lo.w, hi.w);
            uint4 u = make_uint4(*(unsigned*)&q0, *(unsigned*)&q1,
                                 *(unsigned*)&q2, *(unsigned*)&q3);
            *(uint4*)&Bs[k2 * SB + b_c] = u;
        }
    };

    float acc[4][4][4];
    #pragma unroll
    for (int i = 0; i < 4; i++)
        #pragma unroll
        for (int j = 0; j < 4; j++)
            #pragma unroll
            for (int c = 0; c < 4; c++) acc[i][j][c] = 0.f;

    load_W(0);

    if (tid < HID) {
        float mu  = st_sum[tid] * (1.0f / N_NODES);
        float var = st_sq[tid] * (1.0f / N_NODES) - mu * mu;
        float sc  = gma[tid] * rsqrtf(var + BN_EPS);
        s_sc[tid] = sc;
        s_sh[tid] = bta[tid] - mu * sc;
    }
    __syncthreads();

    load_A(0);
    for (int k0 = 0; k0 < K; k0 += 32) {
        store_smem();
        __syncthreads();
        if (k0 + 32 < K) { load_W(k0 + 32); load_A(k0 + 32); }
        #pragma unroll
        for (int s = 0; s < 2; s++) {
            int base = s * 8;
            unsigned afr[4][4], bfr[4][2];
            #pragma unroll
            for (int i = 0; i < 4; i++) {
                int m = wm + i * 16;
                afr[i][0] = As[(m + gid)     * SA + base + tig];
                afr[i][1] = As[(m + gid + 8) * SA + base + tig];
                afr[i][2] = As[(m + gid)     * SA + base + tig + 4];
                afr[i][3] = As[(m + gid + 8) * SA + base + tig + 4];
            }
            #pragma unroll
            for (int j = 0; j < 4; j++) {
                int n = wn + j * 8 + gid;
                bfr[j][0] = Bs[(base + tig)     * SB + n];
                bfr[j][1] = Bs[(base + tig + 4) * SB + n];
            }
            #pragma unroll
            for (int i = 0; i < 4; i++)
                #pragma unroll
                for (int j = 0; j < 4; j++)
                    MMA_FP16(acc[i][j], afr[i], bfr[j]);
        }
        __syncthreads();
    }

    #pragma unroll
    for (int i = 0; i < 4; i++) {
        int r_up = row0 + wm + i * 16 + gid;
        int r_dn = r_up + 8;
        #pragma unroll
        for (int j = 0; j < 4; j++) {
            int col = wn + j * 8 + 2 * tig;
            if (r_up < N_NODES)
                *(__half2*)&C_half[(size_t)r_up * HID + col] =
                    __floats2half2_rn(acc[i][j][0], acc[i][j][1]);
            if (r_dn < N_NODES)
                *(__half2*)&C_half[(size_t)r_dn * HID + col] =
                    __floats2half2_rn(acc[i][j][2], acc[i][j][3]);
        }
    }
}

// ---- aggregation: warp/node, per-warp stats staging (NO shared atomics) ------
__global__ __launch_bounds__(256)
void agg_kernel(const __half* __restrict__ hw, const float* __restrict__ bc,
                float* __restrict__ t, float* __restrict__ st_sum,
                float* __restrict__ st_sq) {
    __shared__ float s_part[8][HID];   // per-warp BN-sum staging
    __shared__ float s_psq[8][HID];    // per-warp BN-sumsq staging
    int tid = threadIdx.x;
    int lane = tid & 31, wid = tid >> 5;
    int n = blockIdx.x * 8 + wid;
    int c = lane * 4;

    int e0 = 0, e1 = 0;
    float di = 0.f;
    unsigned long long r0 = 0, r1 = 0, r2 = 0, r3 = 0;
    if (n < N_NODES) {
        e0 = g_rowptr[n];
        e1 = g_rowptr[n + 1];
        di = g_dinv[n];
        if (e0 < e1)     r0 = __ldg(&g_csr[e0]);
        if (e0 + 1 < e1) r1 = __ldg(&g_csr[e0 + 1]);
        if (e0 + 2 < e1) r2 = __ldg(&g_csr[e0 + 2]);
        if (e0 + 3 < e1) r3 = __ldg(&g_csr[e0 + 3]);
    }

    if (n < N_NODES) {
        float a0 = 0.f, a1 = 0.f, a2 = 0.f, a3 = 0.f;
        for (int e = e0; e < e1; e++) {
            unsigned long long rec = r0;
            r0 = r1; r1 = r2; r2 = r3;
            if (e + 4 < e1) r3 = __ldg(&g_csr[e + 4]);
            unsigned soff = (unsigned)rec;              // s * HID (pre-scaled)
            float wgt = __uint_as_float((unsigned)(rec >> 32));
            uint2 u = __ldg((const uint2*)(hw + soff) + lane);
            float2 f0 = __half22float2(*(const __half2*)&u.x);
            float2 f1 = __half22float2(*(const __half2*)&u.y);
            a0 += f0.x * wgt; a1 += f0.y * wgt; a2 += f1.x * wgt; a3 += f1.y * wgt;
        }
        float dii = di * di;
        uint2 su = __ldg((const uint2*)(hw + (size_t)n * HID) + lane);
        float2 sf0 = __half22float2(*(const __half2*)&su.x);
        float2 sf1 = __half22float2(*(const __half2*)&su.y);
        float t0 = a0 * di + sf0.x * dii + bc[c + 0];
        float t1 = a1 * di + sf0.y * dii + bc[c + 1];
        float t2 = a2 * di + sf1.x * dii + bc[c + 2];
        float t3 = a3 * di + sf1.y * dii + bc[c + 3];
        *(float4*)(t + (size_t)n * HID + c) = make_float4(t0, t1, t2, t3);
        *(float4*)&s_part[wid][c] = make_float4(t0, t1, t2, t3);
        *(float4*)&s_psq[wid][c]  = make_float4(t0 * t0, t1 * t1,
                                                t2 * t2, t3 * t3);
    } else {
        *(float4*)&s_part[wid][c] = make_float4(0.f, 0.f, 0.f, 0.f);
        *(float4*)&s_psq[wid][c]  = make_float4(0.f, 0.f, 0.f, 0.f);
    }
    __syncthreads();
    if (tid < HID) {
        float ssum = 0.f, ssq = 0.f;
        #pragma unroll
        for (int w2 = 0; w2 < 8; w2++) {
            ssum += s_part[w2][tid];
            ssq  += s_psq[w2][tid];
        }
        atomicAdd(&st_sum[tid], ssum);
        atomicAdd(&st_sq[tid],  ssq);
    }
}

// ------- output projection fused with final BN+relu+residual (hres fp16) ------
__global__ __launch_bounds__(256)
void out_kernel(const float* __restrict__ t, const __half* __restrict__ hres,
                const float* __restrict__ st_sum, const float* __restrict__ st_sq,
                const float* __restrict__ gma, const float* __restrict__ bta,
                const float* __restrict__ Wo, const float* __restrict__ bo,
                float* __restrict__ out) {
    __shared__ float ws[HID * OUT_DIM];
    __shared__ float bs[OUT_DIM];
    __shared__ float s_sc[HID], s_sh[HID];
    int tid = threadIdx.x;
    for (int i = tid; i < HID * OUT_DIM; i += blockDim.x) ws[i] = Wo[i];
    if (tid < OUT_DIM) bs[tid] = bo[tid];
    if (tid < HID) {
        float mu  = st_sum[tid] * (1.0f / N_NODES);
        float var = st_sq[tid] * (1.0f / N_NODES) - mu * mu;
        float sc  = gma[tid] * rsqrtf(var + BN_EPS);
        s_sc[tid] = sc;
        s_sh[tid] = bta[tid] - mu * sc;
    }
    __syncthreads();
    int n = blockIdx.x * blockDim.x + tid;
    if (n >= N_NODES) return;
    float acc[OUT_DIM];
    #pragma unroll
    for (int o = 0; o < OUT_DIM; o++) acc[o] = bs[o];
    const float4* tp = (const float4*)(t + (size_t)n * HID);
    const uint2* rp = (const uint2*)(hres + (size_t)n * HID);
    #pragma unroll 4
    for (int k4 = 0; k4 < HID / 4; k4++) {
        float4 tv = tp[k4];
        uint2 ru = rp[k4];
        float2 r01 = __half22float2(*(const __half2*)&ru.x);
        float2 r23 = __half22float2(*(const __half2*)&ru.y);
        int kb = k4 * 4;
        float a0 = fmaxf(tv.x * s_sc[kb + 0] + s_sh[kb + 0], 0.f) + r01.x;
        float a1 = fmaxf(tv.y * s_sc[kb + 1] + s_sh[kb + 1], 0.f) + r01.y;
        float a2 = fmaxf(tv.z * s_sc[kb + 2] + s_sh[kb + 2], 0.f) + r23.x;
        float a3 = fmaxf(tv.w * s_sc[kb + 3] + s_sh[kb + 3], 0.f) + r23.y;
        #pragma unroll
        for (int o = 0; o < OUT_DIM; o++) {
            acc[o] += a0 * ws[(kb + 0) * OUT_DIM + o]
                    + a1 * ws[(kb + 1) * OUT_DIM + o]
                    + a2 * ws[(kb + 2) * OUT_DIM + o]
                    + a3 * ws[(kb + 3) * OUT_DIM + o];
        }
    }
    #pragma unroll
    for (int o = 0; o < OUT_DIM; o++) out[n * OUT_DIM + o] = acc[o];
}

// ---------------- launch ----------------
extern "C" void kernel_launch(void* const* d_in, const int* in_sizes, int n_in,
                              void* d_out, int out_size) {
    const float* x     = (const float*)d_in[0];
    const void*  ei    = d_in[1];
    const float* W_in  = (const float*)d_in[2];
    const float* b_in  = (const float*)d_in[3];
    const float* Wc    = (const float*)d_in[4];
    const float* bc    = (const float*)d_in[5];
    const float* gamma = (const float*)d_in[6];
    const float* beta  = (const float*)d_in[7];
    const float* W_out = (const float*)d_in[8];
    const float* b_out = (const float*)d_in[9];
    float* out = (float*)d_out;

    float *p_t, *p_sum, *p_sq;
    __half *p_hwh, *p_h;
    int* p_deg;
    cudaGetSymbolAddress((void**)&p_h,   g_h);
    cudaGetSymbolAddress((void**)&p_hwh, g_hwh);
    cudaGetSymbolAddress((void**)&p_t,   g_t);
    cudaGetSymbolAddress((void**)&p_sum, g_sum);
    cudaGetSymbolAddress((void**)&p_sq,  g_sumsq);
    cudaGetSymbolAddress((void**)&p_deg, g_deg);

    static cudaStream_t s_side = nullptr;
    static cudaEvent_t ev_fork = nullptr, ev_join = nullptr;
    if (!s_side) {
        cudaStreamCreateWithFlags(&s_side, cudaStreamNonBlocking);
        cudaEventCreateWithFlags(&ev_fork, cudaEventDisableTiming);
        cudaEventCreateWithFlags(&ev_join, cudaEventDisableTiming);
    }

    // BN stats zero: main stream (completes long before agg0)
    cudaMemsetAsync(p_sum, 0, 3 * HID * sizeof(float), 0);
    cudaMemsetAsync(p_sq,  0, 3 * HID * sizeof(float), 0);

    // fork: CSR build on side stream, overlapped with fused input+conv0 GEMM
    cudaEventRecord(ev_fork, 0);
    cudaStreamWaitEvent(s_side, ev_fork, 0);
    cudaMemsetAsync(p_deg, 0, N_NODES * sizeof(int), s_side);
    detect_kernel<<<1, 256, 0, s_side>>>(ei);
    count_deg_kernel<<<586, 1024, 0, s_side>>>(ei);
    scan_write_kernel<<<N_TILES, SCAN_TILE, 0, s_side>>>();
    build_csr_kernel<<<586, 1024, 0, s_side>>>(ei);
    cudaEventRecord(ev_join, s_side);

    int grid = (N_NODES + 127) / 128;
    int agrid = (N_NODES + 7) / 8;

    // fused: hw (fp16) = relu(x @ W_in + b_in) @ Wc0
    gemm_in0_kernel<<<grid, 256>>>(x, W_in, b_in, Wc, p_hwh);

    // join: agg needs CSR
    cudaStreamWaitEvent(0, ev_join, 0);
    agg_kernel<<<agrid, 256>>>(p_hwh, bc, p_t, p_sum, p_sq);

    // layer 1: BN(stats0)+relu fused A-build, writes h1 (fp16) + hw fp16
    gemm_fp16_kernel<<<grid, 256>>>(Wc + 1 * HID * HID, p_hwh,
                                    p_t, p_sum, p_sq, gamma, beta,
                                    nullptr, p_h, 0);
    agg_kernel<<<agrid, 256>>>(p_hwh, bc + HID, p_t, p_sum + HID, p_sq + HID);

    // layer 2: BN(stats1)+relu+res(h1) fused A-build, writes h2 (fp16) + hw fp16
    gemm_fp16_kernel<<<grid, 256>>>(Wc + 2 * HID * HID, p_hwh,
                                    p_t, p_sum + HID, p_sq + HID,
                                    gamma + HID, beta + HID,
                                    p_h, p_h, 1);
    agg_kernel<<<agrid, 256>>>(p_hwh, bc + 2 * HID, p_t,
                               p_sum + 2 * HID, p_sq + 2 * HID);

    // output: fused BN(stats2)+relu+res(h2) then @ W_out + b_out
    out_kernel<<<(N_NODES + 255) / 256, 256>>>(p_t, p_h,
                                               p_sum + 2 * HID, p_sq + 2 * HID,
                                               gamma + 2 * HID, beta + 2 * HID,
                                               W_out, b_out, out);
}